// round 4
// baseline (speedup 1.0000x reference)
#include <cuda_runtime.h>
#include <cuda_bf16.h>

// SiLU y = x*sigmoid(x), streaming fp32.
// R4: persistent grid-stride kernel (152 SMs x 8 CTAs, single wave),
// 4 front-batched LDG.128 per loop iteration, streaming cache hints.

__device__ __forceinline__ float silu1(float x) {
    return x * (1.0f / (1.0f + __expf(-x)));
}

__device__ __forceinline__ float4 silu4(float4 v) {
    float4 r;
    r.x = silu1(v.x);
    r.y = silu1(v.y);
    r.z = silu1(v.z);
    r.w = silu1(v.w);
    return r;
}

#define VPT 4

__global__ void __launch_bounds__(256)
silu_persistent(const float4* __restrict__ in,
                float4* __restrict__ out,
                int n4) {
    const int stride = gridDim.x * blockDim.x;       // in float4 units
    int i = blockIdx.x * blockDim.x + threadIdx.x;

    // Main loop: 4 independent front-batched 128-bit loads per iteration.
    while (i + 3 * stride < n4) {
        float4 v0 = __ldcs(&in[i + 0 * stride]);
        float4 v1 = __ldcs(&in[i + 1 * stride]);
        float4 v2 = __ldcs(&in[i + 2 * stride]);
        float4 v3 = __ldcs(&in[i + 3 * stride]);
        __stcs(&out[i + 0 * stride], silu4(v0));
        __stcs(&out[i + 1 * stride], silu4(v1));
        __stcs(&out[i + 2 * stride], silu4(v2));
        __stcs(&out[i + 3 * stride], silu4(v3));
        i += 4 * stride;
    }
    // Tail: remaining float4s
    while (i < n4) {
        __stcs(&out[i], silu4(__ldcs(&in[i])));
        i += stride;
    }
}

__global__ void silu_kernel_tail(const float* __restrict__ in,
                                 float* __restrict__ out,
                                 int start, int n) {
    int i = start + blockIdx.x * blockDim.x + threadIdx.x;
    if (i < n) out[i] = silu1(in[i]);
}

extern "C" void kernel_launch(void* const* d_in, const int* in_sizes, int n_in,
                              void* d_out, int out_size) {
    const float* x = (const float*)d_in[0];
    float* y = (float*)d_out;
    int n = in_sizes[0];

    int n4 = n / 4;
    if (n4 > 0) {
        const int threads = 256;
        const int blocks = 152 * 8;   // GB300: 152 SMs, 8 CTAs/SM -> one wave
        silu_persistent<<<blocks, threads>>>((const float4*)x, (float4*)y, n4);
    }
    int rem = n - n4 * 4;
    if (rem > 0) {
        silu_kernel_tail<<<1, 256>>>(x, y, n4 * 4, n);
    }
}

// round 5
// speedup vs baseline: 1.1401x; 1.1401x over previous
#include <cuda_runtime.h>
#include <cuda_bf16.h>

// SiLU y = x*sigmoid(x), streaming fp32 over 4*4096*4096 elements.
// R5: proven R2 shape (non-persistent, VPT=4 front-batched LDG.128.cs),
// with all bounds checks removed on the exact-division fast path and
// registers pinned for full occupancy.

__device__ __forceinline__ float silu1(float x) {
    return x * (1.0f / (1.0f + __expf(-x)));
}

__device__ __forceinline__ float4 silu4(float4 v) {
    float4 r;
    r.x = silu1(v.x);
    r.y = silu1(v.y);
    r.z = silu1(v.z);
    r.w = silu1(v.w);
    return r;
}

#define VPT 4

// Exact-fit kernel: grid*block*VPT == n4, no predicates at all.
__global__ void __launch_bounds__(256, 8)
silu_exact(const float4* __restrict__ in, float4* __restrict__ out) {
    int base = blockIdx.x * (256 * VPT) + threadIdx.x;
    float4 v0 = __ldcs(&in[base +   0]);
    float4 v1 = __ldcs(&in[base + 256]);
    float4 v2 = __ldcs(&in[base + 512]);
    float4 v3 = __ldcs(&in[base + 768]);
    __stcs(&out[base +   0], silu4(v0));
    __stcs(&out[base + 256], silu4(v1));
    __stcs(&out[base + 512], silu4(v2));
    __stcs(&out[base + 768], silu4(v3));
}

// Guarded fallback for shapes that don't divide exactly.
__global__ void __launch_bounds__(256, 8)
silu_guarded(const float4* __restrict__ in, float4* __restrict__ out, int n4) {
    int base = blockIdx.x * (256 * VPT) + threadIdx.x;
    #pragma unroll
    for (int k = 0; k < VPT; k++) {
        int i = base + k * 256;
        if (i < n4) __stcs(&out[i], silu4(__ldcs(&in[i])));
    }
}

__global__ void silu_tail(const float* __restrict__ in, float* __restrict__ out,
                          int start, int n) {
    int i = start + blockIdx.x * blockDim.x + threadIdx.x;
    if (i < n) out[i] = silu1(in[i]);
}

extern "C" void kernel_launch(void* const* d_in, const int* in_sizes, int n_in,
                              void* d_out, int out_size) {
    const float* x = (const float*)d_in[0];
    float* y = (float*)d_out;
    int n = in_sizes[0];

    int n4 = n / 4;
    const int threads = 256;
    const int per_block = threads * VPT;  // 1024 float4s per block

    if (n4 > 0) {
        if (n4 % per_block == 0) {
            silu_exact<<<n4 / per_block, threads>>>((const float4*)x, (float4*)y);
        } else {
            int blocks = (n4 + per_block - 1) / per_block;
            silu_guarded<<<blocks, threads>>>((const float4*)x, (float4*)y, n4);
        }
    }
    int rem = n - n4 * 4;
    if (rem > 0) {
        silu_tail<<<1, 256>>>(x, y, n4 * 4, n);
    }
}

// round 6
// speedup vs baseline: 1.1499x; 1.0086x over previous
#include <cuda_runtime.h>
#include <cuda_bf16.h>

// SiLU y = x*sigmoid(x), streaming fp32 over 4*4096*4096 elements.
// R6: block=512 geometry test; exact-fit no-predicate path, VPT=4
// front-batched LDG.128.cs + STG.128.cs (zero-reuse stream).

__device__ __forceinline__ float silu1(float x) {
    return x * (1.0f / (1.0f + __expf(-x)));
}

__device__ __forceinline__ float4 silu4(float4 v) {
    float4 r;
    r.x = silu1(v.x);
    r.y = silu1(v.y);
    r.z = silu1(v.z);
    r.w = silu1(v.w);
    return r;
}

#define VPT 4
#define TPB 512

// Exact-fit kernel: grid*TPB*VPT == n4, no predicates.
__global__ void __launch_bounds__(TPB, 4)
silu_exact512(const float4* __restrict__ in, float4* __restrict__ out) {
    int base = blockIdx.x * (TPB * VPT) + threadIdx.x;
    float4 v0 = __ldcs(&in[base + 0 * TPB]);
    float4 v1 = __ldcs(&in[base + 1 * TPB]);
    float4 v2 = __ldcs(&in[base + 2 * TPB]);
    float4 v3 = __ldcs(&in[base + 3 * TPB]);
    __stcs(&out[base + 0 * TPB], silu4(v0));
    __stcs(&out[base + 1 * TPB], silu4(v1));
    __stcs(&out[base + 2 * TPB], silu4(v2));
    __stcs(&out[base + 3 * TPB], silu4(v3));
}

// Guarded fallback for non-dividing shapes.
__global__ void __launch_bounds__(TPB, 4)
silu_guarded(const float4* __restrict__ in, float4* __restrict__ out, int n4) {
    int base = blockIdx.x * (TPB * VPT) + threadIdx.x;
    #pragma unroll
    for (int k = 0; k < VPT; k++) {
        int i = base + k * TPB;
        if (i < n4) __stcs(&out[i], silu4(__ldcs(&in[i])));
    }
}

__global__ void silu_tail(const float* __restrict__ in, float* __restrict__ out,
                          int start, int n) {
    int i = start + blockIdx.x * blockDim.x + threadIdx.x;
    if (i < n) out[i] = silu1(in[i]);
}

extern "C" void kernel_launch(void* const* d_in, const int* in_sizes, int n_in,
                              void* d_out, int out_size) {
    const float* x = (const float*)d_in[0];
    float* y = (float*)d_out;
    int n = in_sizes[0];

    int n4 = n / 4;
    const int per_block = TPB * VPT;  // 2048 float4s per block

    if (n4 > 0) {
        if (n4 % per_block == 0) {
            silu_exact512<<<n4 / per_block, TPB>>>((const float4*)x, (float4*)y);
        } else {
            int blocks = (n4 + per_block - 1) / per_block;
            silu_guarded<<<blocks, TPB>>>((const float4*)x, (float4*)y, n4);
        }
    }
    int rem = n - n4 * 4;
    if (rem > 0) {
        silu_tail<<<1, 256>>>(x, y, n4 * 4, n);
    }
}